// round 9
// baseline (speedup 1.0000x reference)
#include <cuda_runtime.h>
#include <cuda_bf16.h>
#include <cstdint>

#define USER_NUM 80000
#define ITEM_NUM 40000
#define NTOT     (USER_NUM + ITEM_NUM)   // 120000
#define EMB      64
#define NNZ      1200000
#define N_LAYERS 3

#define TOTAL_F  (NTOT * EMB)            // 7,680,000 floats
#define TOTAL_V4 (TOTAL_F / 4)           // 1,920,000 float4

#define CAP      64                      // ELL row capacity (Poisson λ=10; P(>=64) ~ 1e-30)

// Scratch (allocation-free rule: __device__ globals)
__device__ float g_bufA[TOTAL_F];
__device__ float g_bufB[TOTAL_F];
__device__ int   g_cnt[NTOT];                       // per-row cursor/count
__device__ int2  g_ell[(size_t)NTOT * CAP];         // (col, val_bits) slots — 61.4 MB

// ---------------------------------------------------------------------------
// zero the per-row cursors
// ---------------------------------------------------------------------------
__global__ void zero_cnt_kernel() {
    int i = blockIdx.x * blockDim.x + threadIdx.x;
    if (i < NTOT) g_cnt[i] = 0;
}

// ---------------------------------------------------------------------------
// fill ELL: one pass, no prefix sums.
// pos = cursor[r]++ ; ell[r*CAP + pos] = (col, val)
// ---------------------------------------------------------------------------
__global__ void fill_ell_kernel(const float* __restrict__ vals,
                                const int*   __restrict__ rows,
                                const int*   __restrict__ cols) {
    int e = blockIdx.x * blockDim.x + threadIdx.x;
    if (e >= NNZ) return;
    int r = rows[e];
    int pos = atomicAdd(&g_cnt[r], 1);
    if (pos < CAP) {
        int2 m;
        m.x = cols[e];
        m.y = __float_as_int(vals[e]);
        g_ell[(size_t)r * CAP + pos] = m;
    }
}

// ---------------------------------------------------------------------------
// Fused ELL SpMM + layer accumulate.
// 16 threads per row; each thread owns one float4 column slice.
//   y[r] = sum_k val * x[col]   (register accumulation, unroll-2, dual acc)
//   out[r] (+)= y[r] / 3
// Gather source: col < split -> xa[col], else xb[col - split]
//   layer 0 : xa=user_emb, xb=item_emb, split=USER_NUM  (no init pass needed)
//   layer 1+: xa=xb=buf,   split=NTOT
// last==1 skips the y store. No atomics anywhere.
// ---------------------------------------------------------------------------
__global__ void spmm_fused_kernel(const float* __restrict__ xa,
                                  const float* __restrict__ xb,
                                  int split,
                                  float*       __restrict__ y,
                                  float4*      __restrict__ out4,
                                  int first, int last) {
    int t = blockIdx.x * blockDim.x + threadIdx.x;
    if (t >= NTOT * 16) return;
    int r = t >> 4;
    int c = (t & 15) * 4;

    int n = g_cnt[r];
    if (n > CAP) n = CAP;
    const int2* row = g_ell + (size_t)r * CAP;

    float4 acc0 = make_float4(0.f, 0.f, 0.f, 0.f);
    float4 acc1 = make_float4(0.f, 0.f, 0.f, 0.f);

    int k = 0;
    for (; k + 2 <= n; k += 2) {
        int2 m0 = row[k];
        int2 m1 = row[k + 1];
        const float* p0 = (m0.x < split) ? xa + (size_t)m0.x * EMB
                                         : xb + (size_t)(m0.x - split) * EMB;
        const float* p1 = (m1.x < split) ? xa + (size_t)m1.x * EMB
                                         : xb + (size_t)(m1.x - split) * EMB;
        float4 xv0 = *reinterpret_cast<const float4*>(p0 + c);
        float4 xv1 = *reinterpret_cast<const float4*>(p1 + c);
        float v0 = __int_as_float(m0.y);
        float v1 = __int_as_float(m1.y);
        acc0.x += v0 * xv0.x; acc0.y += v0 * xv0.y;
        acc0.z += v0 * xv0.z; acc0.w += v0 * xv0.w;
        acc1.x += v1 * xv1.x; acc1.y += v1 * xv1.y;
        acc1.z += v1 * xv1.z; acc1.w += v1 * xv1.w;
    }
    if (k < n) {
        int2 m0 = row[k];
        const float* p0 = (m0.x < split) ? xa + (size_t)m0.x * EMB
                                         : xb + (size_t)(m0.x - split) * EMB;
        float4 xv0 = *reinterpret_cast<const float4*>(p0 + c);
        float v0 = __int_as_float(m0.y);
        acc0.x += v0 * xv0.x; acc0.y += v0 * xv0.y;
        acc0.z += v0 * xv0.z; acc0.w += v0 * xv0.w;
    }

    float4 acc;
    acc.x = acc0.x + acc1.x; acc.y = acc0.y + acc1.y;
    acc.z = acc0.z + acc1.z; acc.w = acc0.w + acc1.w;

    size_t o = (size_t)t;                             // r*16 + lane
    if (!last) reinterpret_cast<float4*>(y)[o] = acc;

    const float inv3 = 1.0f / 3.0f;
    float4 res;
    if (first) {
        res.x = acc.x * inv3; res.y = acc.y * inv3;
        res.z = acc.z * inv3; res.w = acc.w * inv3;
    } else {
        float4 a = out4[o];
        res.x = a.x + acc.x * inv3; res.y = a.y + acc.y * inv3;
        res.z = a.z + acc.z * inv3; res.w = a.w + acc.w * inv3;
    }
    out4[o] = res;
}

// ---------------------------------------------------------------------------
// launch: 5 kernel launches, trivially graph-capturable.
// ---------------------------------------------------------------------------
extern "C" void kernel_launch(void* const* d_in, const int* in_sizes, int n_in,
                              void* d_out, int out_size) {
    const float* user_emb = (const float*)d_in[0];
    const float* item_emb = (const float*)d_in[1];
    const float* adj_vals = (const float*)d_in[2];
    const int*   adj_rows = (const int*)d_in[3];
    const int*   adj_cols = (const int*)d_in[4];
    float4* out = (float4*)d_out;

    float *A, *B;
    cudaGetSymbolAddress((void**)&A, g_bufA);
    cudaGetSymbolAddress((void**)&B, g_bufB);

    const int TB = 256;
    const int gridN = (NTOT + TB - 1) / TB;           // 469
    const int gridE = (NNZ + TB - 1) / TB;            // 4688
    const int gridS = (NTOT * 16 + TB - 1) / TB;      // 7500

    // ELL build: zero cursors, then single-pass fill (no scans)
    zero_cnt_kernel<<<gridN, TB>>>();
    fill_ell_kernel<<<gridE, TB>>>(adj_vals, adj_rows, adj_cols);

    // Layer 0: gather straight from inputs -> B ; out  = B/3
    spmm_fused_kernel<<<gridS, TB>>>(user_emb, item_emb, USER_NUM, B, out, 1, 0);
    // Layer 1: B -> A ; out += A/3
    spmm_fused_kernel<<<gridS, TB>>>(B, B, NTOT, A, out, 0, 0);
    // Layer 2: A -> (skip store) ; out += y/3
    spmm_fused_kernel<<<gridS, TB>>>(A, A, NTOT, B, out, 0, 1);
}

// round 11
// speedup vs baseline: 1.3579x; 1.3579x over previous
#include <cuda_runtime.h>
#include <cuda_bf16.h>
#include <cstdint>

#define USER_NUM 80000
#define ITEM_NUM 40000
#define NTOT     (USER_NUM + ITEM_NUM)   // 120000
#define EMB      64
#define NNZ      1200000
#define N_LAYERS 3

#define TOTAL_F  (NTOT * EMB)            // 7,680,000 floats
#define TOTAL_V4 (TOTAL_F / 4)           // 1,920,000 float4

#define SCAN_BS  1024
#define NBLK     ((NTOT + SCAN_BS - 1) / SCAN_BS)   // 118

// Scratch (allocation-free rule: __device__ globals)
__device__ float g_bufA[TOTAL_F];
__device__ float g_bufB[TOTAL_F];
__device__ int   g_cnt[NTOT];
__device__ int   g_rowptr[NTOT + 1];
__device__ int   g_cursor[NTOT];
__device__ int   g_blocksums[NBLK];
__device__ int2  g_sorted[NNZ];          // (col, val_bits), grouped by row — dense 9.6 MB

// ---------------------------------------------------------------------------
// Stage 1: histogram of row counts
// ---------------------------------------------------------------------------
__global__ void zero_cnt_kernel() {
    int i = blockIdx.x * blockDim.x + threadIdx.x;
    if (i < NTOT) g_cnt[i] = 0;
}

__global__ void hist_kernel(const int* __restrict__ rows) {
    int e = blockIdx.x * blockDim.x + threadIdx.x;
    if (e < NNZ) atomicAdd(&g_cnt[rows[e]], 1);
}

// ---------------------------------------------------------------------------
// Stage 2: exclusive scan of g_cnt -> g_rowptr (two-level)
// ---------------------------------------------------------------------------
__global__ void scan_blocks_kernel() {
    __shared__ int s[SCAN_BS];
    int b = blockIdx.x, t = threadIdx.x;
    int i = b * SCAN_BS + t;
    int v = (i < NTOT) ? g_cnt[i] : 0;
    s[t] = v;
    __syncthreads();
    for (int off = 1; off < SCAN_BS; off <<= 1) {
        int add = (t >= off) ? s[t - off] : 0;
        __syncthreads();
        s[t] += add;
        __syncthreads();
    }
    if (i < NTOT) g_rowptr[i] = s[t] - v;            // exclusive within block
    if (t == SCAN_BS - 1) g_blocksums[b] = s[t];      // block total
}

__global__ void scan_sums_kernel() {                  // 1 block, 128 threads
    __shared__ int s[128];
    int t = threadIdx.x;
    int v = (t < NBLK) ? g_blocksums[t] : 0;
    s[t] = v;
    __syncthreads();
    for (int off = 1; off < 128; off <<= 1) {
        int add = (t >= off) ? s[t - off] : 0;
        __syncthreads();
        s[t] += add;
        __syncthreads();
    }
    if (t < NBLK) g_blocksums[t] = s[t] - v;          // exclusive
}

__global__ void add_offsets_kernel() {
    int i = blockIdx.x * blockDim.x + threadIdx.x;
    if (i < NTOT) {
        int rp = g_rowptr[i] + g_blocksums[i / SCAN_BS];
        g_rowptr[i] = rp;
        g_cursor[i] = rp;
    }
    if (i == 0) g_rowptr[NTOT] = NNZ;
}

// ---------------------------------------------------------------------------
// Stage 3: scatter edges into row-grouped order
// ---------------------------------------------------------------------------
__global__ void scatter_kernel(const float* __restrict__ vals,
                               const int*   __restrict__ rows,
                               const int*   __restrict__ cols) {
    int e = blockIdx.x * blockDim.x + threadIdx.x;
    if (e >= NNZ) return;
    int r = rows[e];
    int pos = atomicAdd(&g_cursor[r], 1);
    int2 m;
    m.x = cols[e];
    m.y = __float_as_int(vals[e]);
    g_sorted[pos] = m;
}

// ---------------------------------------------------------------------------
// Fused CSR SpMM + layer accumulate.
// 16 threads per row; each thread owns one float4 column slice.
//   y[r] = sum_{e in row r} val * x[col]   (registers, unroll-2, dual acc)
//   out[r] (+)= y[r] / 3
// Gather source: col < split -> xa[col], else xb[col - split]
//   layer 0 : xa=user_emb, xb=item_emb, split=USER_NUM  (no init pass)
//   layer 1+: xa=xb=buf,   split=NTOT
// last==1 skips the y store. No atomics anywhere in the layers.
// ---------------------------------------------------------------------------
__global__ void spmm_fused_kernel(const float* __restrict__ xa,
                                  const float* __restrict__ xb,
                                  int split,
                                  float*       __restrict__ y,
                                  float4*      __restrict__ out4,
                                  int first, int last) {
    int t = blockIdx.x * blockDim.x + threadIdx.x;
    if (t >= NTOT * 16) return;
    int r = t >> 4;
    int c = (t & 15) * 4;

    int beg = __ldg(&g_rowptr[r]);
    int end = __ldg(&g_rowptr[r + 1]);

    float4 acc0 = make_float4(0.f, 0.f, 0.f, 0.f);
    float4 acc1 = make_float4(0.f, 0.f, 0.f, 0.f);

    int k = beg;
    for (; k + 2 <= end; k += 2) {
        int2 m0 = __ldg(&g_sorted[k]);
        int2 m1 = __ldg(&g_sorted[k + 1]);
        const float* p0 = (m0.x < split) ? xa + (size_t)m0.x * EMB
                                         : xb + (size_t)(m0.x - split) * EMB;
        const float* p1 = (m1.x < split) ? xa + (size_t)m1.x * EMB
                                         : xb + (size_t)(m1.x - split) * EMB;
        float4 xv0 = *reinterpret_cast<const float4*>(p0 + c);
        float4 xv1 = *reinterpret_cast<const float4*>(p1 + c);
        float v0 = __int_as_float(m0.y);
        float v1 = __int_as_float(m1.y);
        acc0.x += v0 * xv0.x; acc0.y += v0 * xv0.y;
        acc0.z += v0 * xv0.z; acc0.w += v0 * xv0.w;
        acc1.x += v1 * xv1.x; acc1.y += v1 * xv1.y;
        acc1.z += v1 * xv1.z; acc1.w += v1 * xv1.w;
    }
    if (k < end) {
        int2 m0 = __ldg(&g_sorted[k]);
        const float* p0 = (m0.x < split) ? xa + (size_t)m0.x * EMB
                                         : xb + (size_t)(m0.x - split) * EMB;
        float4 xv0 = *reinterpret_cast<const float4*>(p0 + c);
        float v0 = __int_as_float(m0.y);
        acc0.x += v0 * xv0.x; acc0.y += v0 * xv0.y;
        acc0.z += v0 * xv0.z; acc0.w += v0 * xv0.w;
    }

    float4 acc;
    acc.x = acc0.x + acc1.x; acc.y = acc0.y + acc1.y;
    acc.z = acc0.z + acc1.z; acc.w = acc0.w + acc1.w;

    size_t o = (size_t)t;                             // r*16 + lane
    if (!last) reinterpret_cast<float4*>(y)[o] = acc;

    const float inv3 = 1.0f / 3.0f;
    float4 res;
    if (first) {
        res.x = acc.x * inv3; res.y = acc.y * inv3;
        res.z = acc.z * inv3; res.w = acc.w * inv3;
    } else {
        float4 a = out4[o];
        res.x = a.x + acc.x * inv3; res.y = a.y + acc.y * inv3;
        res.z = a.z + acc.z * inv3; res.w = a.w + acc.w * inv3;
    }
    out4[o] = res;
}

// ---------------------------------------------------------------------------
// launch: 9 kernel launches, trivially graph-capturable.
// ---------------------------------------------------------------------------
extern "C" void kernel_launch(void* const* d_in, const int* in_sizes, int n_in,
                              void* d_out, int out_size) {
    const float* user_emb = (const float*)d_in[0];
    const float* item_emb = (const float*)d_in[1];
    const float* adj_vals = (const float*)d_in[2];
    const int*   adj_rows = (const int*)d_in[3];
    const int*   adj_cols = (const int*)d_in[4];
    float4* out = (float4*)d_out;

    float *A, *B;
    cudaGetSymbolAddress((void**)&A, g_bufA);
    cudaGetSymbolAddress((void**)&B, g_bufB);

    const int TB = 256;
    const int gridN = (NTOT + TB - 1) / TB;           // 469
    const int gridE = (NNZ + TB - 1) / TB;            // 4688
    const int gridS = (NTOT * 16 + TB - 1) / TB;      // 7500

    // CSR build (counting sort by row)
    zero_cnt_kernel<<<gridN, TB>>>();
    hist_kernel<<<gridE, TB>>>(adj_rows);
    scan_blocks_kernel<<<NBLK, SCAN_BS>>>();
    scan_sums_kernel<<<1, 128>>>();
    add_offsets_kernel<<<gridN, TB>>>();
    scatter_kernel<<<gridE, TB>>>(adj_vals, adj_rows, adj_cols);

    // Layer 0: gather straight from inputs -> B ; out  = B/3
    spmm_fused_kernel<<<gridS, TB>>>(user_emb, item_emb, USER_NUM, B, out, 1, 0);
    // Layer 1: B -> A ; out += A/3
    spmm_fused_kernel<<<gridS, TB>>>(B, B, NTOT, A, out, 0, 0);
    // Layer 2: A -> (skip store) ; out += y/3
    spmm_fused_kernel<<<gridS, TB>>>(A, A, NTOT, B, out, 0, 1);
}